// round 7
// baseline (speedup 1.0000x reference)
#include <cuda_runtime.h>
#include <cuda_bf16.h>
#include <cstdint>

// TopKRouter: mma.sync bf16 2-way split (hh+hm+mh), warp tile m32 x n64,
// split-K 4-way across warps. A-frags direct from gmem, B-frags pre-packed.
// TM=32 tokens/CTA, 4 warps (K quarters), grid 512.
// out (f32): [0,32768) topk_idx ; [32768,65536) topk_probs ; [65536,..) probs.

#define D_DIM   2048
#define E_DIM   64
#define BSZ     16384
#define TM      32
#define KC      32
#define NCHUNK  (D_DIM / KC)
#define THREADS 128
#define EPS     1e-9f
#define LS_STRIDE 65

// B fragments: [c(64)][ks(2)][s(2)][g(4)][lane(32)] uint4
__device__ uint4 g_bfrag[NCHUNK * 2 * 2 * 4 * 32];

__device__ __forceinline__ uint32_t pack2(__nv_bfloat16 a, __nv_bfloat16 b) {
    __nv_bfloat162 t; t.x = a; t.y = b;
    return *(uint32_t*)&t;
}
__device__ __forceinline__ __nv_bfloat16 split_sel(float v, int s) {
    __nv_bfloat16 bh = __float2bfloat16_rn(v);
    if (s == 0) return bh;
    return __float2bfloat16_rn(v - __bfloat162float(bh));
}

__global__ void prep_w_kernel(const float* __restrict__ w) {
    int t = blockIdx.x * blockDim.x + threadIdx.x;
    if (t >= NCHUNK * 2 * 2 * 4 * 32) return;
    int lane = t & 31;
    int rest = t >> 5;
    int g  = rest & 3;  rest >>= 2;
    int s  = rest & 1;  rest >>= 1;
    int ks = rest & 1;  rest >>= 1;
    int c  = rest;
    uint32_t r[4];
    #pragma unroll
    for (int tt = 0; tt < 2; tt++) {
        int n = (g * 2 + tt) * 8 + (lane >> 2);
        #pragma unroll
        for (int bb = 0; bb < 2; bb++) {
            int k0 = c * KC + ks * 16 + bb * 8 + 2 * (lane & 3);
            float v0 = w[(size_t)n * D_DIM + k0];
            float v1 = w[(size_t)n * D_DIM + k0 + 1];
            r[tt * 2 + bb] = pack2(split_sel(v0, s), split_sel(v1, s));
        }
    }
    g_bfrag[t] = make_uint4(r[0], r[1], r[2], r[3]);
}

__device__ __forceinline__ void mma16816(float* d, const uint32_t* a,
                                         uint32_t b0, uint32_t b1) {
    asm volatile(
        "mma.sync.aligned.m16n8k16.row.col.f32.bf16.bf16.f32 "
        "{%0,%1,%2,%3}, {%4,%5,%6,%7}, {%8,%9}, {%0,%1,%2,%3};"
        : "+f"(d[0]), "+f"(d[1]), "+f"(d[2]), "+f"(d[3])
        : "r"(a[0]), "r"(a[1]), "r"(a[2]), "r"(a[3]), "r"(b0), "r"(b1));
}

// pack float2 -> bf16x2 (hi = v.y, lo = v.x) and residual bf16x2
__device__ __forceinline__ void cvt_split(float2 v, uint32_t& h, uint32_t& m) {
    asm("cvt.rn.bf16x2.f32 %0, %1, %2;" : "=r"(h) : "f"(v.y), "f"(v.x));
    float h0 = __uint_as_float(h << 16);
    float h1 = __uint_as_float(h & 0xffff0000u);
    float r0 = v.x - h0;
    float r1 = v.y - h1;
    asm("cvt.rn.bf16x2.f32 %0, %1, %2;" : "=r"(m) : "f"(r1), "f"(r0));
}

__global__ __launch_bounds__(THREADS, 4)
void topk_router_mma(const float* __restrict__ x, float* __restrict__ out)
{
    __shared__ float ls[TM][LS_STRIDE];

    const int tid  = threadIdx.x;
    const int wid  = tid >> 5;     // K quarter 0..3
    const int lane = tid & 31;
    const int m0   = blockIdx.x * TM;
    const int r    = lane >> 2;
    const int t4   = lane & 3;

    // 4 row pointers: rows r, r+8, r+16, r+24 of this CTA's 32-token tile
    const float* xr[4];
    #pragma unroll
    for (int j = 0; j < 4; j++)
        xr[j] = x + (size_t)(m0 + r + j * 8) * D_DIM + t4 * 2;

    float acc[2][8][4];
    #pragma unroll
    for (int mt = 0; mt < 2; mt++)
        #pragma unroll
        for (int j = 0; j < 8; j++)
            #pragma unroll
            for (int q = 0; q < 4; q++) acc[mt][j][q] = 0.0f;

    const int c0 = wid * (NCHUNK / 4);

    #pragma unroll 1
    for (int c = c0; c < c0 + NCHUNK / 4; c++) {
        #pragma unroll
        for (int ks = 0; ks < 2; ks++) {
            const int kb = c * KC + ks * 16;

            // A fragments for both m16 tiles: 8 LDG.64
            uint32_t ah[2][4], am[2][4];
            #pragma unroll
            for (int mt = 0; mt < 2; mt++) {
                float2 v0 = *(const float2*)&xr[mt * 2 + 0][kb];
                float2 v1 = *(const float2*)&xr[mt * 2 + 1][kb];
                float2 v2 = *(const float2*)&xr[mt * 2 + 0][kb + 8];
                float2 v3 = *(const float2*)&xr[mt * 2 + 1][kb + 8];
                cvt_split(v0, ah[mt][0], am[mt][0]);
                cvt_split(v1, ah[mt][1], am[mt][1]);
                cvt_split(v2, ah[mt][2], am[mt][2]);
                cvt_split(v3, ah[mt][3], am[mt][3]);
            }

            // B fragments, consumed per n16 group g
            const int fb = ((c * 2 + ks) * 2) * 128 + lane;
            #pragma unroll
            for (int g = 0; g < 4; g++) {
                uint4 qh = g_bfrag[fb + g * 32];
                uint4 qm = g_bfrag[fb + 128 + g * 32];
                #pragma unroll
                for (int mt = 0; mt < 2; mt++) {
                    mma16816(acc[mt][2*g],   ah[mt], qh.x, qh.y);   // hh
                    mma16816(acc[mt][2*g+1], ah[mt], qh.z, qh.w);
                    mma16816(acc[mt][2*g],   ah[mt], qm.x, qm.y);   // hm
                    mma16816(acc[mt][2*g+1], ah[mt], qm.z, qm.w);
                    mma16816(acc[mt][2*g],   am[mt], qh.x, qh.y);   // mh
                    mma16816(acc[mt][2*g+1], am[mt], qh.z, qh.w);
                }
            }
        }
    }

    // ---- split-K 4-way combine in smem ----
    const int colb = 2 * (lane & 3);
    #pragma unroll 1
    for (int q = 0; q < 4; q++) {
        if (wid == q) {
            #pragma unroll
            for (int mt = 0; mt < 2; mt++) {
                int row = mt * 16 + r;
                #pragma unroll
                for (int j = 0; j < 8; j++) {
                    if (q == 0) {
                        ls[row][colb + j * 8]         = acc[mt][j][0];
                        ls[row][colb + j * 8 + 1]     = acc[mt][j][1];
                        ls[row + 8][colb + j * 8]     = acc[mt][j][2];
                        ls[row + 8][colb + j * 8 + 1] = acc[mt][j][3];
                    } else {
                        ls[row][colb + j * 8]         += acc[mt][j][0];
                        ls[row][colb + j * 8 + 1]     += acc[mt][j][1];
                        ls[row + 8][colb + j * 8]     += acc[mt][j][2];
                        ls[row + 8][colb + j * 8 + 1] += acc[mt][j][3];
                    }
                }
            }
        }
        __syncthreads();
    }

    // ---- softmax + top-2, one token per thread ----
    if (tid < TM) {
        const int token = m0 + tid;
        float* row_p = &ls[tid][0];

        float mx = -1e30f;
        #pragma unroll
        for (int e = 0; e < E_DIM; e++) mx = fmaxf(mx, row_p[e]);

        float sum = 0.0f;
        #pragma unroll
        for (int e = 0; e < E_DIM; e++) {
            float ev = expf(row_p[e] - mx);
            row_p[e] = ev;
            sum += ev;
        }
        float inv = 1.0f / sum;

        float* __restrict__ out_p = out + 4 * BSZ + (size_t)token * E_DIM;
        float p1 = -1.0f, p2 = -1.0f;
        int   i1 = 0,     i2 = 0;
        #pragma unroll
        for (int e = 0; e < E_DIM; e += 4) {
            float4 pv = make_float4(row_p[e] * inv, row_p[e+1] * inv,
                                    row_p[e+2] * inv, row_p[e+3] * inv);
            *(float4*)&out_p[e] = pv;
            float pe[4] = {pv.x, pv.y, pv.z, pv.w};
            #pragma unroll
            for (int j = 0; j < 4; j++) {
                if (pe[j] > p1)      { p2 = p1; i2 = i1; p1 = pe[j]; i1 = e + j; }
                else if (pe[j] > p2) { p2 = pe[j]; i2 = e + j; }
            }
        }

        float denom = p1 + p2 + EPS;
        out[token * 2 + 0] = (float)i1;
        out[token * 2 + 1] = (float)i2;
        out[2 * BSZ + token * 2 + 0] = p1 / denom;
        out[2 * BSZ + token * 2 + 1] = p2 / denom;
    }
}

extern "C" void kernel_launch(void* const* d_in, const int* in_sizes, int n_in,
                              void* d_out, int out_size)
{
    const float* x = (const float*)d_in[0];
    const float* w = (const float*)d_in[1];
    float* out = (float*)d_out;

    prep_w_kernel<<<(NCHUNK * 2 * 2 * 4 * 32 + 255) / 256, 256>>>(w);
    topk_router_mma<<<BSZ / TM, THREADS>>>(x, out);
}

// round 8
// speedup vs baseline: 1.0509x; 1.0509x over previous
#include <cuda_runtime.h>
#include <cuda_bf16.h>
#include <cstdint>

// TopKRouter: mma.sync bf16 2-way split (hh+hm+mh), warp tile m16 x n64,
// split-K 4-way across warps, TM=16, grid 1024 (high occupancy).
// A-frags direct from gmem; B-frags pre-packed per-lane in gmem (L1/L2-hot).
// out (f32): [0,32768) topk_idx ; [32768,65536) topk_probs ; [65536,..) probs.

#define D_DIM   2048
#define E_DIM   64
#define BSZ     16384
#define TM      16
#define KC      32
#define NCHUNK  (D_DIM / KC)
#define THREADS 128
#define EPS     1e-9f
#define LS_STRIDE 66

// B fragments: [c(64)][ks(2)][s(2)][g(4)][lane(32)] uint4
__device__ uint4 g_bfrag[NCHUNK * 2 * 2 * 4 * 32];

__device__ __forceinline__ uint32_t pack2(__nv_bfloat16 a, __nv_bfloat16 b) {
    __nv_bfloat162 t; t.x = a; t.y = b;
    return *(uint32_t*)&t;
}
__device__ __forceinline__ __nv_bfloat16 split_sel(float v, int s) {
    __nv_bfloat16 bh = __float2bfloat16_rn(v);
    if (s == 0) return bh;
    return __float2bfloat16_rn(v - __bfloat162float(bh));
}

__global__ void prep_w_kernel(const float* __restrict__ w) {
    int t = blockIdx.x * blockDim.x + threadIdx.x;
    if (t >= NCHUNK * 2 * 2 * 4 * 32) return;
    int lane = t & 31;
    int rest = t >> 5;
    int g  = rest & 3;  rest >>= 2;
    int s  = rest & 1;  rest >>= 1;
    int ks = rest & 1;  rest >>= 1;
    int c  = rest;
    uint32_t r[4];
    #pragma unroll
    for (int tt = 0; tt < 2; tt++) {
        int n = (g * 2 + tt) * 8 + (lane >> 2);
        #pragma unroll
        for (int bb = 0; bb < 2; bb++) {
            int k0 = c * KC + ks * 16 + bb * 8 + 2 * (lane & 3);
            float v0 = w[(size_t)n * D_DIM + k0];
            float v1 = w[(size_t)n * D_DIM + k0 + 1];
            r[tt * 2 + bb] = pack2(split_sel(v0, s), split_sel(v1, s));
        }
    }
    g_bfrag[t] = make_uint4(r[0], r[1], r[2], r[3]);
}

__device__ __forceinline__ void mma16816(float* d, const uint32_t* a,
                                         uint32_t b0, uint32_t b1) {
    asm volatile(
        "mma.sync.aligned.m16n8k16.row.col.f32.bf16.bf16.f32 "
        "{%0,%1,%2,%3}, {%4,%5,%6,%7}, {%8,%9}, {%0,%1,%2,%3};"
        : "+f"(d[0]), "+f"(d[1]), "+f"(d[2]), "+f"(d[3])
        : "r"(a[0]), "r"(a[1]), "r"(a[2]), "r"(a[3]), "r"(b0), "r"(b1));
}

// pack float2 -> bf16x2 (hi = v.y, lo = v.x) and residual bf16x2
__device__ __forceinline__ void cvt_split(float2 v, uint32_t& h, uint32_t& m) {
    asm("cvt.rn.bf16x2.f32 %0, %1, %2;" : "=r"(h) : "f"(v.y), "f"(v.x));
    float h0 = __uint_as_float(h << 16);
    float h1 = __uint_as_float(h & 0xffff0000u);
    float r0 = v.x - h0;
    float r1 = v.y - h1;
    asm("cvt.rn.bf16x2.f32 %0, %1, %2;" : "=r"(m) : "f"(r1), "f"(r0));
}

__global__ __launch_bounds__(THREADS, 5)
void topk_router_mma(const float* __restrict__ x, float* __restrict__ out)
{
    __shared__ float ls[2][TM][LS_STRIDE];

    const int tid  = threadIdx.x;
    const int wid  = tid >> 5;     // K quarter 0..3
    const int lane = tid & 31;
    const int m0   = blockIdx.x * TM;
    const int r    = lane >> 2;
    const int t4   = lane & 3;

    const float* xr0 = x + (size_t)(m0 + r)     * D_DIM + t4 * 2;
    const float* xr1 = x + (size_t)(m0 + r + 8) * D_DIM + t4 * 2;

    float acc[8][4];
    #pragma unroll
    for (int j = 0; j < 8; j++)
        #pragma unroll
        for (int q = 0; q < 4; q++) acc[j][q] = 0.0f;

    const int c0 = wid * (NCHUNK / 4);

    #pragma unroll 1
    for (int c = c0; c < c0 + NCHUNK / 4; c++) {
        #pragma unroll
        for (int ks = 0; ks < 2; ks++) {
            // B fragments (L1/L2-hot): 8 x LDG.128
            const int fb = ((c * 2 + ks) * 2) * 128 + lane;
            uint4 qh[4], qm[4];
            #pragma unroll
            for (int gg = 0; gg < 4; gg++) {
                qh[gg] = g_bfrag[fb + gg * 32];
                qm[gg] = g_bfrag[fb + 128 + gg * 32];
            }

            // A fragments: 4 x LDG.64 straight from x
            const int kb = c * KC + ks * 16;
            float2 v0 = *(const float2*)&xr0[kb];
            float2 v1 = *(const float2*)&xr1[kb];
            float2 v2 = *(const float2*)&xr0[kb + 8];
            float2 v3 = *(const float2*)&xr1[kb + 8];

            uint32_t ah[4], am[4];
            cvt_split(v0, ah[0], am[0]);
            cvt_split(v1, ah[1], am[1]);
            cvt_split(v2, ah[2], am[2]);
            cvt_split(v3, ah[3], am[3]);

            #pragma unroll
            for (int gg = 0; gg < 4; gg++) {
                mma16816(acc[2*gg],   ah, qh[gg].x, qh[gg].y);   // hh
                mma16816(acc[2*gg+1], ah, qh[gg].z, qh[gg].w);
                mma16816(acc[2*gg],   ah, qm[gg].x, qm[gg].y);   // hm
                mma16816(acc[2*gg+1], ah, qm[gg].z, qm[gg].w);
                mma16816(acc[2*gg],   am, qh[gg].x, qh[gg].y);   // mh
                mma16816(acc[2*gg+1], am, qh[gg].z, qh[gg].w);
            }
        }
    }

    // ---- split-K combine: warps 0,1 write two partial buffers; 2,3 add ----
    const int colb = 2 * (lane & 3);
    const int half = wid & 1;

    if (wid < 2) {
        #pragma unroll
        for (int j = 0; j < 8; j++) {
            ls[half][r][colb + j * 8]         = acc[j][0];
            ls[half][r][colb + j * 8 + 1]     = acc[j][1];
            ls[half][r + 8][colb + j * 8]     = acc[j][2];
            ls[half][r + 8][colb + j * 8 + 1] = acc[j][3];
        }
    }
    __syncthreads();
    if (wid >= 2) {
        #pragma unroll
        for (int j = 0; j < 8; j++) {
            ls[half][r][colb + j * 8]         += acc[j][0];
            ls[half][r][colb + j * 8 + 1]     += acc[j][1];
            ls[half][r + 8][colb + j * 8]     += acc[j][2];
            ls[half][r + 8][colb + j * 8 + 1] += acc[j][3];
        }
    }
    __syncthreads();

    // ---- softmax + top-2, one token per thread (16 tokens) ----
    if (tid < TM) {
        const int token = m0 + tid;
        const float* r0p = &ls[0][tid][0];
        const float* r1p = &ls[1][tid][0];

        float lv[E_DIM];
        float mx = -1e30f;
        #pragma unroll
        for (int e = 0; e < E_DIM; e++) {
            lv[e] = r0p[e] + r1p[e];
            mx = fmaxf(mx, lv[e]);
        }

        float sum = 0.0f;
        #pragma unroll
        for (int e = 0; e < E_DIM; e++) {
            lv[e] = expf(lv[e] - mx);
            sum += lv[e];
        }
        float inv = 1.0f / sum;

        float* __restrict__ out_p = out + 4 * BSZ + (size_t)token * E_DIM;
        float p1 = -1.0f, p2 = -1.0f;
        int   i1 = 0,     i2 = 0;
        #pragma unroll
        for (int e = 0; e < E_DIM; e += 4) {
            float4 pv = make_float4(lv[e] * inv, lv[e+1] * inv,
                                    lv[e+2] * inv, lv[e+3] * inv);
            *(float4*)&out_p[e] = pv;
            float pe[4] = {pv.x, pv.y, pv.z, pv.w};
            #pragma unroll
            for (int j = 0; j < 4; j++) {
                if (pe[j] > p1)      { p2 = p1; i2 = i1; p1 = pe[j]; i1 = e + j; }
                else if (pe[j] > p2) { p2 = pe[j]; i2 = e + j; }
            }
        }

        float denom = p1 + p2 + EPS;
        out[token * 2 + 0] = (float)i1;
        out[token * 2 + 1] = (float)i2;
        out[2 * BSZ + token * 2 + 0] = p1 / denom;
        out[2 * BSZ + token * 2 + 1] = p2 / denom;
    }
}

extern "C" void kernel_launch(void* const* d_in, const int* in_sizes, int n_in,
                              void* d_out, int out_size)
{
    const float* x = (const float*)d_in[0];
    const float* w = (const float*)d_in[1];
    float* out = (float*)d_out;

    prep_w_kernel<<<(NCHUNK * 2 * 2 * 4 * 32 + 255) / 256, 256>>>(w);
    topk_router_mma<<<BSZ / TM, THREADS>>>(x, out);
}

// round 10
// speedup vs baseline: 1.3416x; 1.2766x over previous
#include <cuda_runtime.h>
#include <cuda_bf16.h>
#include <cstdint>

// TopKRouter: mma.sync bf16 2-way split (hh+hm+mh), m16n64 warp tile,
// TM=32 (2 m-stripes x 2 K-halves), grid 512. Register double-buffered
// pipeline; A loaded as float4 with k-permuted fragment layout.
// out (f32): [0,32768) topk_idx ; [32768,65536) topk_probs ; [65536,..) probs.

#define D_DIM   2048
#define E_DIM   64
#define BSZ     16384
#define TM      32
#define NK16    (D_DIM / 16)    // 128 k16-steps total
#define THREADS 128
#define EPS     1e-9f
#define LS_STRIDE 65

// B fragments: [i(128 k16-steps)][s(2)][g(4)][lane(32)] uint4
__device__ uint4 g_bfrag[NK16 * 2 * 4 * 32];

__device__ __forceinline__ uint32_t pack2(__nv_bfloat16 a, __nv_bfloat16 b) {
    __nv_bfloat162 t; t.x = a; t.y = b;
    return *(uint32_t*)&t;
}
__device__ __forceinline__ __nv_bfloat16 split_sel(float v, int s) {
    __nv_bfloat16 bh = __float2bfloat16_rn(v);
    if (s == 0) return bh;
    return __float2bfloat16_rn(v - __bfloat162float(bh));
}

// k-PERMUTED layout: within a k16 step, fragment k-slot pairs map to real k:
//   slots (2t, 2t+1)   -> real k = 4t + 0,1
//   slots (2t+8, 2t+9) -> real k = 4t + 2,3      (t = lane&3)
// so A lanes can load one float4 (real k 4t..4t+3) per row.
__global__ void prep_w_kernel(const float* __restrict__ w) {
    int t = blockIdx.x * blockDim.x + threadIdx.x;
    if (t >= NK16 * 2 * 4 * 32) return;
    int lane = t & 31;
    int rest = t >> 5;
    int g  = rest & 3;  rest >>= 2;
    int s  = rest & 1;  rest >>= 1;
    int i  = rest;                      // k16 step 0..127
    uint32_t r[4];
    #pragma unroll
    for (int tt = 0; tt < 2; tt++) {
        int n = (g * 2 + tt) * 8 + (lane >> 2);
        #pragma unroll
        for (int bb = 0; bb < 2; bb++) {
            int k0 = i * 16 + 4 * (lane & 3) + bb * 2;   // permuted
            float v0 = w[(size_t)n * D_DIM + k0];
            float v1 = w[(size_t)n * D_DIM + k0 + 1];
            r[tt * 2 + bb] = pack2(split_sel(v0, s), split_sel(v1, s));
        }
    }
    g_bfrag[t] = make_uint4(r[0], r[1], r[2], r[3]);
}

__device__ __forceinline__ void mma16816(float* d, const uint32_t* a,
                                         uint32_t b0, uint32_t b1) {
    asm volatile(
        "mma.sync.aligned.m16n8k16.row.col.f32.bf16.bf16.f32 "
        "{%0,%1,%2,%3}, {%4,%5,%6,%7}, {%8,%9}, {%0,%1,%2,%3};"
        : "+f"(d[0]), "+f"(d[1]), "+f"(d[2]), "+f"(d[3])
        : "r"(a[0]), "r"(a[1]), "r"(a[2]), "r"(a[3]), "r"(b0), "r"(b1));
}

__device__ __forceinline__ void cvt_split(float vx, float vy,
                                          uint32_t& h, uint32_t& m) {
    asm("cvt.rn.bf16x2.f32 %0, %1, %2;" : "=r"(h) : "f"(vy), "f"(vx));
    float h0 = __uint_as_float(h << 16);
    float h1 = __uint_as_float(h & 0xffff0000u);
    float r0 = vx - h0;
    float r1 = vy - h1;
    asm("cvt.rn.bf16x2.f32 %0, %1, %2;" : "=r"(m) : "f"(r1), "f"(r0));
}

__global__ __launch_bounds__(THREADS, 4)
void topk_router_mma(const float* __restrict__ x, float* __restrict__ out)
{
    __shared__ float ls[TM][LS_STRIDE];

    const int tid  = threadIdx.x;
    const int wid  = tid >> 5;
    const int lane = tid & 31;
    const int ms   = wid & 1;      // m-stripe (16 rows)
    const int kg   = wid >> 1;     // K half
    const int m0w  = blockIdx.x * TM + ms * 16;
    const int r    = lane >> 2;
    const int t4   = lane & 3;

    const float* xr0 = x + (size_t)(m0w + r)     * D_DIM + t4 * 4;
    const float* xr1 = x + (size_t)(m0w + r + 8) * D_DIM + t4 * 4;

    float acc[8][4];
    #pragma unroll
    for (int j = 0; j < 8; j++)
        #pragma unroll
        for (int q = 0; q < 4; q++) acc[j][q] = 0.0f;

    const int HALF = NK16 / 2;         // 64 k16-steps per warp
    const int i0 = kg * HALF;

    float4 a0[2], a1[2];
    uint4 qh[2][4], qm[2][4];

    // prologue: load iteration 0 into buffer 0
    {
        const int ii = i0;
        a0[0] = *(const float4*)&xr0[ii * 16];
        a1[0] = *(const float4*)&xr1[ii * 16];
        const uint4* pb = g_bfrag + (size_t)ii * 256 + lane;
        #pragma unroll
        for (int g = 0; g < 4; g++) {
            qh[0][g] = pb[g * 32];
            qm[0][g] = pb[128 + g * 32];
        }
    }

    #pragma unroll 2
    for (int i = 0; i < HALF; i++) {
        const int cb = i & 1, nb = cb ^ 1;

        // prefetch iteration i+1 into the other buffer
        if (i + 1 < HALF) {
            const int ii = i0 + i + 1;
            a0[nb] = *(const float4*)&xr0[ii * 16];
            a1[nb] = *(const float4*)&xr1[ii * 16];
            const uint4* pb = g_bfrag + (size_t)ii * 256 + lane;
            #pragma unroll
            for (int g = 0; g < 4; g++) {
                qh[nb][g] = pb[g * 32];
                qm[nb][g] = pb[128 + g * 32];
            }
        }

        // convert A (k-permuted): x,y -> low k slots; z,w -> high k slots
        uint32_t ah[4], am[4];
        cvt_split(a0[cb].x, a0[cb].y, ah[0], am[0]);
        cvt_split(a1[cb].x, a1[cb].y, ah[1], am[1]);
        cvt_split(a0[cb].z, a0[cb].w, ah[2], am[2]);
        cvt_split(a1[cb].z, a1[cb].w, ah[3], am[3]);

        #pragma unroll
        for (int g = 0; g < 4; g++) {
            mma16816(acc[2*g],   ah, qh[cb][g].x, qh[cb][g].y);   // hh
            mma16816(acc[2*g+1], ah, qh[cb][g].z, qh[cb][g].w);
            mma16816(acc[2*g],   ah, qm[cb][g].x, qm[cb][g].y);   // hm
            mma16816(acc[2*g+1], ah, qm[cb][g].z, qm[cb][g].w);
            mma16816(acc[2*g],   am, qh[cb][g].x, qh[cb][g].y);   // mh
            mma16816(acc[2*g+1], am, qh[cb][g].z, qh[cb][g].w);
        }
    }

    // ---- combine K halves + stash logits ----
    const int row  = ms * 16 + r;
    const int colb = 2 * t4;

    if (kg == 1) {
        #pragma unroll
        for (int j = 0; j < 8; j++) {
            ls[row][colb + j * 8]         = acc[j][0];
            ls[row][colb + j * 8 + 1]     = acc[j][1];
            ls[row + 8][colb + j * 8]     = acc[j][2];
            ls[row + 8][colb + j * 8 + 1] = acc[j][3];
        }
    }
    __syncthreads();
    if (kg == 0) {
        #pragma unroll
        for (int j = 0; j < 8; j++) {
            ls[row][colb + j * 8]         += acc[j][0];
            ls[row][colb + j * 8 + 1]     += acc[j][1];
            ls[row + 8][colb + j * 8]     += acc[j][2];
            ls[row + 8][colb + j * 8 + 1] += acc[j][3];
        }
    }
    __syncthreads();

    // ---- softmax + top-2, one token per thread ----
    if (tid < TM) {
        const int token = blockIdx.x * TM + tid;
        float* row_p = &ls[tid][0];

        float mx = -1e30f;
        #pragma unroll
        for (int e = 0; e < E_DIM; e++) mx = fmaxf(mx, row_p[e]);

        float sum = 0.0f;
        #pragma unroll
        for (int e = 0; e < E_DIM; e++) {
            float ev = expf(row_p[e] - mx);
            row_p[e] = ev;
            sum += ev;
        }
        float inv = 1.0f / sum;

        float* __restrict__ out_p = out + 4 * BSZ + (size_t)token * E_DIM;
        float p1 = -1.0f, p2 = -1.0f;
        int   i1 = 0,     i2 = 0;
        #pragma unroll
        for (int e = 0; e < E_DIM; e += 4) {
            float4 pv = make_float4(row_p[e] * inv, row_p[e+1] * inv,
                                    row_p[e+2] * inv, row_p[e+3] * inv);
            *(float4*)&out_p[e] = pv;
            float pe[4] = {pv.x, pv.y, pv.z, pv.w};
            #pragma unroll
            for (int j = 0; j < 4; j++) {
                if (pe[j] > p1)      { p2 = p1; i2 = i1; p1 = pe[j]; i1 = e + j; }
                else if (pe[j] > p2) { p2 = pe[j]; i2 = e + j; }
            }
        }

        float denom = p1 + p2 + EPS;
        out[token * 2 + 0] = (float)i1;
        out[token * 2 + 1] = (float)i2;
        out[2 * BSZ + token * 2 + 0] = p1 / denom;
        out[2 * BSZ + token * 2 + 1] = p2 / denom;
    }
}

extern "C" void kernel_launch(void* const* d_in, const int* in_sizes, int n_in,
                              void* d_out, int out_size)
{
    const float* x = (const float*)d_in[0];
    const float* w = (const float*)d_in[1];
    float* out = (float*)d_out;

    prep_w_kernel<<<(NK16 * 2 * 4 * 32 + 255) / 256, 256>>>(w);
    topk_router_mma<<<BSZ / TM, THREADS>>>(x, out);
}